// round 1
// baseline (speedup 1.0000x reference)
#include <cuda_runtime.h>

// ============================================================================
// Detector: out = patches @ (w_patch @ [w_reg|w_obj]) + bias, then anchor decode.
// Algebraic fusion: feat (32768x768) is never materialized.
//   kA1: partial W2[pc][j] = sum_d w_patch[pc][d] * wcat[d][j] over d-chunks
//   kA2: reduce 8 partials -> g_W2 [768][48] (j 45..47 zero pad)
//   kB : per cell, gather 768-float patch from img, dot with W2 (f32x2 FMA),
//        add bias, decode anchors, coalesced store.
// ============================================================================

#define DIMD 768
#define NJ   48        // 45 real columns (36 reg + 9 obj), padded to 48
#define CP   264       // smem cell stride (256 cells + 8 pad)

typedef unsigned long long ull;

__device__ float g_part[8 * DIMD * NJ];   // 1.18 MB scratch (static, allowed)
__device__ float g_W2[DIMD * NJ];

// ---------------------------------------------------------------------------
// kA1: W2 partials. grid (192, 8), block 192. thread = (pc_local 0..3, j 0..47)
// ---------------------------------------------------------------------------
__global__ void kA1(const float* __restrict__ w_patch,
                    const float* __restrict__ w_reg,
                    const float* __restrict__ w_obj)
{
    int j   = threadIdx.x % 48;
    int pcl = threadIdx.x / 48;
    int pc  = blockIdx.x * 4 + pcl;
    int d0  = blockIdx.y * 96;
    float acc = 0.f;
    const float* wp = w_patch + (size_t)pc * DIMD + d0;
    if (j < 36) {
        const float* wr = w_reg + (size_t)d0 * 36 + j;
        #pragma unroll 8
        for (int d = 0; d < 96; ++d) acc += wp[d] * wr[d * 36];
    } else if (j < 45) {
        const float* wo = w_obj + (size_t)d0 * 9 + (j - 36);
        #pragma unroll 8
        for (int d = 0; d < 96; ++d) acc += wp[d] * wo[d * 9];
    }
    g_part[((size_t)blockIdx.y * DIMD + pc) * NJ + j] = acc;
}

// ---------------------------------------------------------------------------
// kA2: deterministic 8-way reduce of partials into g_W2.
// ---------------------------------------------------------------------------
__global__ void kA2()
{
    int idx = blockIdx.x * 256 + threadIdx.x;
    if (idx < DIMD * NJ) {
        float s = 0.f;
        #pragma unroll
        for (int p = 0; p < 8; ++p) s += g_part[p * DIMD * NJ + idx];
        g_W2[idx] = s;
    }
}

// ---------------------------------------------------------------------------
// kB: fused gather-GEMM + decode.
// grid 128 (= 32 b * 4 fy-blocks), block 256. 256 cells per CTA
// (8 fy rows x 32 fx). Thread = (jg 0..3, cellg 0..63): 4 cells x 12 j,
// accumulated as 4x6 f32x2 pairs (j-pairs packed, a duplicated).
// img staged per (c,py) chunk: 8 contiguous 2KB rows -> smem [px][cell],
// register transpose, double buffered.
// ---------------------------------------------------------------------------
__global__ void __launch_bounds__(256, 1) kB(
    const float* __restrict__ img,
    const float* __restrict__ b_reg,
    const float* __restrict__ b_obj,
    float* __restrict__ out)
{
    extern __shared__ float sm[];
    float* sWs   = sm;                       // [768][48] = 36864 floats
    float* sA    = sm + DIMD * NJ;           // [2][16][CP] = 8448 floats
    float* sBias = sA + 2 * 16 * CP;         // [48]

    const int tid  = threadIdx.x;
    const int bidx = blockIdx.x;             // 0..127
    const int b    = bidx >> 2;
    const int fyb  = bidx & 3;

    // ---- load W2 into smem (coalesced float4), load bias ----
    {
        const float4* src = (const float4*)g_W2;
        float4*       dst = (float4*)sWs;
        #pragma unroll
        for (int i = 0; i < 36; ++i)
            dst[tid + 256 * i] = src[tid + 256 * i];
    }
    if (tid < 48)
        sBias[tid] = (tid < 36) ? b_reg[tid] : ((tid < 45) ? b_obj[tid - 36] : 0.f);

    const int jg = tid >> 6;                 // 0..3  (12 j's each)
    const int cg = tid & 63;                 // 0..63 (4 cells each)

    ull acc[4][6];
    #pragma unroll
    for (int c = 0; c < 4; ++c)
        #pragma unroll
        for (int p = 0; p < 6; ++p) acc[c][p] = 0ull;

    // loader mapping: thread loads 16 consecutive floats of one img row
    const int lr    = tid >> 5;              // 0..7 local fy row
    const int lx0   = (tid & 31) << 4;       // x start 0..496
    const int cellw = (lr << 5) + (tid & 31);// cell whose px column we write

    float4 v0, v1, v2, v3;
    // preload chunk 0 (c=0, py=0)
    {
        const float4* src = (const float4*)(img +
            ((((size_t)b * 3 + 0) * 512 + (size_t)(fyb * 8 + lr) * 16 + 0) * 512 + lx0));
        v0 = src[0]; v1 = src[1]; v2 = src[2]; v3 = src[3];
        float* d = sA + cellw;
        d[ 0*CP]=v0.x; d[ 1*CP]=v0.y; d[ 2*CP]=v0.z; d[ 3*CP]=v0.w;
        d[ 4*CP]=v1.x; d[ 5*CP]=v1.y; d[ 6*CP]=v1.z; d[ 7*CP]=v1.w;
        d[ 8*CP]=v2.x; d[ 9*CP]=v2.y; d[10*CP]=v2.z; d[11*CP]=v2.w;
        d[12*CP]=v3.x; d[13*CP]=v3.y; d[14*CP]=v3.z; d[15*CP]=v3.w;
    }
    __syncthreads();

    for (int ch = 0; ch < 48; ++ch) {        // 48 chunks = 3 c * 16 py
        const int cur = ch & 1;
        if (ch < 47) {
            const int nc = ch + 1;
            const int c  = nc >> 4;
            const int py = nc & 15;
            const float4* src = (const float4*)(img +
                ((((size_t)b * 3 + c) * 512 + (size_t)((fyb * 8 + lr) * 16 + py)) * 512 + lx0));
            v0 = src[0]; v1 = src[1]; v2 = src[2]; v3 = src[3];
        }

        const float* wbase = sWs + (ch << 4) * NJ + jg * 12;
        const float* abase = sA + cur * (16 * CP) + (cg << 2);
        #pragma unroll
        for (int px = 0; px < 16; ++px) {
            float4 av = *(const float4*)(abase + px * CP);        // 4 cells, conflict-free
            const float* wrow = wbase + px * NJ;
            ulonglong2 wA = *(const ulonglong2*)(wrow);           // j pairs 0-1,2-3
            ulonglong2 wB = *(const ulonglong2*)(wrow + 4);       // 4-5,6-7
            ulonglong2 wC = *(const ulonglong2*)(wrow + 8);       // 8-9,10-11
            const ull w0 = wA.x, w1 = wA.y, w2 = wB.x, w3 = wB.y, w4 = wC.x, w5 = wC.y;
            #pragma unroll
            for (int cc = 0; cc < 4; ++cc) {
                float a = (cc == 0) ? av.x : (cc == 1) ? av.y : (cc == 2) ? av.z : av.w;
                ull aa;
                asm("mov.b64 %0, {%1, %1};" : "=l"(aa) : "f"(a));
                asm("fma.rn.f32x2 %0, %1, %2, %0;" : "+l"(acc[cc][0]) : "l"(aa), "l"(w0));
                asm("fma.rn.f32x2 %0, %1, %2, %0;" : "+l"(acc[cc][1]) : "l"(aa), "l"(w1));
                asm("fma.rn.f32x2 %0, %1, %2, %0;" : "+l"(acc[cc][2]) : "l"(aa), "l"(w2));
                asm("fma.rn.f32x2 %0, %1, %2, %0;" : "+l"(acc[cc][3]) : "l"(aa), "l"(w3));
                asm("fma.rn.f32x2 %0, %1, %2, %0;" : "+l"(acc[cc][4]) : "l"(aa), "l"(w4));
                asm("fma.rn.f32x2 %0, %1, %2, %0;" : "+l"(acc[cc][5]) : "l"(aa), "l"(w5));
            }
        }

        if (ch < 47) {
            float* d = sA + (cur ^ 1) * (16 * CP) + cellw;
            d[ 0*CP]=v0.x; d[ 1*CP]=v0.y; d[ 2*CP]=v0.z; d[ 3*CP]=v0.w;
            d[ 4*CP]=v1.x; d[ 5*CP]=v1.y; d[ 6*CP]=v1.z; d[ 7*CP]=v1.w;
            d[ 8*CP]=v2.x; d[ 9*CP]=v2.y; d[10*CP]=v2.z; d[11*CP]=v2.w;
            d[12*CP]=v3.x; d[13*CP]=v3.y; d[14*CP]=v3.z; d[15*CP]=v3.w;
        }
        __syncthreads();
    }

    // ---- epilogue: gather per-cell 48 values (reuse sWs region), decode ----
    float* sOut = sm;                         // [256][49]
    #pragma unroll
    for (int cc = 0; cc < 4; ++cc) {
        const int cell = (cg << 2) + cc;
        #pragma unroll
        for (int p = 0; p < 6; ++p) {
            float2 v = *(float2*)&acc[cc][p];
            const int j = jg * 12 + p * 2;
            sOut[cell * 49 + j]     = v.x + sBias[j];
            sOut[cell * 49 + j + 1] = v.y + sBias[j + 1];
        }
    }
    __syncthreads();

    float* sStage = sm + 256 * 49;            // [2304][7]
    {
        const int cell = tid;
        const int m  = bidx * 256 + cell;     // global cell = ((b*32+fy)*32+fx)
        const float fx = (float)(m & 31);
        const float fy = (float)((m >> 5) & 31);
        const float bb = (float)(m >> 10);
        #pragma unroll
        for (int k = 0; k < 9; ++k) {
            const float r0 = sOut[cell * 49 + 4 * k + 0];
            const float r1 = sOut[cell * 49 + 4 * k + 1];
            const float r2 = sOut[cell * 49 + 4 * k + 2];
            const float r3 = sOut[cell * 49 + 4 * k + 3];
            const float lg = sOut[cell * 49 + 36 + k];
            const float BW = (k % 3 == 0) ? 2.f : ((k % 3 == 1) ? 4.f : 8.f);
            const float BH = (k / 3 == 0) ? 2.f : ((k / 3 == 1) ? 4.f : 8.f);
            const float wc = fx * 16.f + r0;
            const float hc = fy * 16.f + r1;
            const float wa = wc + BW * r2;
            const float ha = hc + BH * r3;
            const float ob = 1.f / (1.f + __expf(-lg));
            float* o = sStage + (cell * 9 + k) * 7;
            o[0] = wc; o[1] = hc; o[2] = wa; o[3] = ha;
            o[4] = bb; o[5] = ob; o[6] = (float)k;
        }
    }
    __syncthreads();

    // coalesced block-contiguous store: 256 cells * 9 anchors * 7 = 16128 floats
    float* obase = out + (size_t)bidx * 16128;
    #pragma unroll
    for (int i = 0; i < 63; ++i)
        obase[tid + 256 * i] = sStage[tid + 256 * i];
}

// ---------------------------------------------------------------------------
extern "C" void kernel_launch(void* const* d_in, const int* in_sizes, int n_in,
                              void* d_out, int out_size)
{
    const float* img     = (const float*)d_in[0];
    const float* w_patch = (const float*)d_in[1];
    const float* w_reg   = (const float*)d_in[2];
    const float* b_reg   = (const float*)d_in[3];
    const float* w_obj   = (const float*)d_in[4];
    const float* b_obj   = (const float*)d_in[5];
    float* out = (float*)d_out;

    kA1<<<dim3(192, 8), 192>>>(w_patch, w_reg, w_obj);
    kA2<<<144, 256>>>();

    const size_t SMEM = (size_t)(DIMD * NJ + 2 * 16 * CP + 48) * sizeof(float); // 181,440 B
    cudaFuncSetAttribute(kB, cudaFuncAttributeMaxDynamicSharedMemorySize, (int)SMEM);
    kB<<<128, 256, SMEM>>>(img, b_reg, b_obj, out);
}

// round 2
// speedup vs baseline: 1.0239x; 1.0239x over previous
#include <cuda_runtime.h>

// ============================================================================
// Detector: out = patches @ (w_patch @ [w_reg|w_obj]) + bias, then anchor decode.
// feat never materialized.
//   kA1: W2 partials with smem-staged weights (grid 48x8, block 192)
//   kA2: reduce 8 partials -> g_W2 [768][48]
//   kB : fused gather-GEMM (c=8 cells x j=8 per thread, d-split halves,
//        block 384) + decode + coalesced store.
// ============================================================================

#define DIMD 768
#define NJ   48
#define CP   264
#define WPP  97

typedef unsigned long long ull;

__device__ float g_part[8 * DIMD * NJ];
__device__ float g_W2[DIMD * NJ];

// ---------------------------------------------------------------------------
// kA1: grid (48, 8), block 192. CTA: 16 pc-rows x 96 d-chunk x 48 j.
// thread = (rl = tid/12, jq = tid%12): float4 over j.
// ---------------------------------------------------------------------------
__global__ void __launch_bounds__(192) kA1(const float* __restrict__ w_patch,
                                           const float* __restrict__ w_reg,
                                           const float* __restrict__ w_obj)
{
    __shared__ float sWc[96 * 48];
    __shared__ float sWp[16 * WPP];

    const int tid = threadIdx.x;
    const int d0  = blockIdx.y * 96;
    const int r0  = blockIdx.x * 16;

    for (int i = tid; i < 96 * 36; i += 192) {
        int d = i / 36, jj = i % 36;
        sWc[d * 48 + jj] = w_reg[(size_t)(d0 + d) * 36 + jj];
    }
    for (int i = tid; i < 96 * 9; i += 192) {
        int d = i / 9, jj = i % 9;
        sWc[d * 48 + 36 + jj] = w_obj[(size_t)(d0 + d) * 9 + jj];
    }
    for (int i = tid; i < 96 * 3; i += 192)
        sWc[(i / 3) * 48 + 45 + (i % 3)] = 0.f;
    for (int i = tid; i < 16 * 96; i += 192) {
        int r = i / 96, dd = i % 96;
        sWp[r * WPP + dd] = w_patch[(size_t)(r0 + r) * DIMD + d0 + dd];
    }
    __syncthreads();

    const int rl = tid / 12;
    const int jq = tid % 12;
    float4 acc = make_float4(0.f, 0.f, 0.f, 0.f);
    #pragma unroll 8
    for (int dd = 0; dd < 96; ++dd) {
        float a = sWp[rl * WPP + dd];
        float4 w4 = *(const float4*)&sWc[dd * 48 + jq * 4];
        acc.x += a * w4.x; acc.y += a * w4.y;
        acc.z += a * w4.z; acc.w += a * w4.w;
    }
    ((float4*)g_part)[((size_t)blockIdx.y * DIMD + r0 + rl) * 12 + jq] = acc;
}

// ---------------------------------------------------------------------------
__global__ void kA2()
{
    int idx = blockIdx.x * 256 + threadIdx.x;   // 9216 float4s
    const float4* p = (const float4*)g_part;
    float4 s = make_float4(0.f, 0.f, 0.f, 0.f);
    #pragma unroll
    for (int k = 0; k < 8; ++k) {
        float4 v = p[k * 9216 + idx];
        s.x += v.x; s.y += v.y; s.z += v.z; s.w += v.w;
    }
    ((float4*)g_W2)[idx] = s;
}

// ---------------------------------------------------------------------------
// kB: grid 128 (32 b x 4 fyb), block 384. 256 cells/CTA.
// thread = (dh = tid/192, jg = (tid%192)/32, cg = tid%32):
//   8 cells (cg*4..+3 and 128+cg*4..+3) x 8 j (jg*8..+7), px half dh.
// ---------------------------------------------------------------------------
__global__ void __launch_bounds__(384, 1) kB(
    const float* __restrict__ img,
    const float* __restrict__ b_reg,
    const float* __restrict__ b_obj,
    float* __restrict__ out)
{
    extern __shared__ float sm[];
    float* sWs   = sm;                        // [768][48] = 36864
    float* sA    = sm + DIMD * NJ;            // [2][16][CP] = 8448
    float* sBias = sA + 2 * 16 * CP;          // [48]  (sm + 45312)

    const int tid  = threadIdx.x;
    const int bidx = blockIdx.x;
    const int b    = bidx >> 2;
    const int fyb  = bidx & 3;

    // W2 -> smem (9216 float4 / 384 = 24 each)
    {
        const float4* src = (const float4*)g_W2;
        float4*       dst = (float4*)sWs;
        #pragma unroll
        for (int i = 0; i < 24; ++i)
            dst[tid + 384 * i] = src[tid + 384 * i];
    }
    if (tid < 48)
        sBias[tid] = (tid < 36) ? b_reg[tid] : ((tid < 45) ? b_obj[tid - 36] : 0.f);

    const int dh = tid / 192;
    const int t2 = tid % 192;
    const int jg = t2 / 32;                   // 0..5, warp-uniform
    const int cg = t2 % 32;
    const int pxb = dh * 8;

    ull acc[8][4];
    #pragma unroll
    for (int c = 0; c < 8; ++c)
        #pragma unroll
        for (int p = 0; p < 4; ++p) acc[c][p] = 0ull;

    // loader mapping (tid < 256)
    const int lr    = (tid & 255) >> 5;
    const int lx0   = (tid & 31) << 4;
    const int cellw = (lr << 5) + (tid & 31);
    const bool isldr = (tid < 256);

    float4 v0, v1, v2, v3;
    if (isldr) {
        const float4* src = (const float4*)(img +
            ((((size_t)b * 3 + 0) * 512 + (size_t)(fyb * 8 + lr) * 16) * 512 + lx0));
        v0 = src[0]; v1 = src[1]; v2 = src[2]; v3 = src[3];
        float* d = sA + cellw;
        d[ 0*CP]=v0.x; d[ 1*CP]=v0.y; d[ 2*CP]=v0.z; d[ 3*CP]=v0.w;
        d[ 4*CP]=v1.x; d[ 5*CP]=v1.y; d[ 6*CP]=v1.z; d[ 7*CP]=v1.w;
        d[ 8*CP]=v2.x; d[ 9*CP]=v2.y; d[10*CP]=v2.z; d[11*CP]=v2.w;
        d[12*CP]=v3.x; d[13*CP]=v3.y; d[14*CP]=v3.z; d[15*CP]=v3.w;
    }
    __syncthreads();

    for (int ch = 0; ch < 48; ++ch) {
        const int cur = ch & 1;
        if (isldr && ch < 47) {
            const int nc = ch + 1;
            const int c  = nc >> 4;
            const int py = nc & 15;
            const float4* src = (const float4*)(img +
                ((((size_t)b * 3 + c) * 512 + (size_t)((fyb * 8 + lr) * 16 + py)) * 512 + lx0));
            v0 = src[0]; v1 = src[1]; v2 = src[2]; v3 = src[3];
        }

        const float* wbase = sWs + ((ch << 4) + pxb) * NJ + jg * 8;
        const float* abase = sA + cur * (16 * CP) + pxb * CP + (cg << 2);
        #pragma unroll
        for (int px = 0; px < 8; ++px) {
            float4 av1 = *(const float4*)(abase + px * CP);
            float4 av2 = *(const float4*)(abase + px * CP + 128);
            const float* wrow = wbase + px * NJ;
            ulonglong2 wA = *(const ulonglong2*)(wrow);       // j +0/1, +2/3
            ulonglong2 wB = *(const ulonglong2*)(wrow + 4);   // j +4/5, +6/7
            const ull w0 = wA.x, w1 = wA.y, w2 = wB.x, w3 = wB.y;
            #pragma unroll
            for (int cc = 0; cc < 8; ++cc) {
                float a = (cc == 0) ? av1.x : (cc == 1) ? av1.y :
                          (cc == 2) ? av1.z : (cc == 3) ? av1.w :
                          (cc == 4) ? av2.x : (cc == 5) ? av2.y :
                          (cc == 6) ? av2.z : av2.w;
                ull aa;
                asm("mov.b64 %0, {%1, %1};" : "=l"(aa) : "f"(a));
                asm("fma.rn.f32x2 %0, %1, %2, %0;" : "+l"(acc[cc][0]) : "l"(aa), "l"(w0));
                asm("fma.rn.f32x2 %0, %1, %2, %0;" : "+l"(acc[cc][1]) : "l"(aa), "l"(w1));
                asm("fma.rn.f32x2 %0, %1, %2, %0;" : "+l"(acc[cc][2]) : "l"(aa), "l"(w2));
                asm("fma.rn.f32x2 %0, %1, %2, %0;" : "+l"(acc[cc][3]) : "l"(aa), "l"(w3));
            }
        }

        if (isldr && ch < 47) {
            float* d = sA + (cur ^ 1) * (16 * CP) + cellw;
            d[ 0*CP]=v0.x; d[ 1*CP]=v0.y; d[ 2*CP]=v0.z; d[ 3*CP]=v0.w;
            d[ 4*CP]=v1.x; d[ 5*CP]=v1.y; d[ 6*CP]=v1.z; d[ 7*CP]=v1.w;
            d[ 8*CP]=v2.x; d[ 9*CP]=v2.y; d[10*CP]=v2.z; d[11*CP]=v2.w;
            d[12*CP]=v3.x; d[13*CP]=v3.y; d[14*CP]=v3.z; d[15*CP]=v3.w;
        }
        __syncthreads();
    }

    // ---- merge dh halves via smem (reuse W2 region: 192*32 ull = 12288 fl) ----
    ull* sM = (ull*)sm;
    if (tid >= 192) {
        #pragma unroll
        for (int cc = 0; cc < 8; ++cc)
            #pragma unroll
            for (int p = 0; p < 4; ++p)
                sM[(size_t)(tid - 192) * 32 + cc * 4 + p] = acc[cc][p];
    }
    __syncthreads();
    if (tid < 192) {
        #pragma unroll
        for (int cc = 0; cc < 8; ++cc)
            #pragma unroll
            for (int p = 0; p < 4; ++p) {
                ull o = sM[(size_t)tid * 32 + cc * 4 + p];
                asm("add.rn.f32x2 %0, %0, %1;" : "+l"(acc[cc][p]) : "l"(o));
            }
    }
    __syncthreads();

    // ---- gather per-cell 48 j values ----
    float* sOut = sm + 12288;                 // [256][49] = 12544 (ends 24832)
    if (tid < 192) {
        #pragma unroll
        for (int cc = 0; cc < 8; ++cc) {
            const int cell = (cc < 4) ? (cg * 4 + cc) : (128 + cg * 4 + cc - 4);
            #pragma unroll
            for (int p = 0; p < 4; ++p) {
                float2 v = *(float2*)&acc[cc][p];
                const int j = jg * 8 + p * 2;
                sOut[cell * 49 + j]     = v.x + sBias[j];
                sOut[cell * 49 + j + 1] = v.y + sBias[j + 1];
            }
        }
    }
    __syncthreads();

    // ---- decode ----
    float* sStage = sm + 24832;               // [2304][7] = 16128 (ends 40960)
    if (tid < 256) {
        const int cell = tid;
        const int m  = bidx * 256 + cell;
        const float fx = (float)(m & 31);
        const float fy = (float)((m >> 5) & 31);
        const float bb = (float)(m >> 10);
        #pragma unroll
        for (int k = 0; k < 9; ++k) {
            const float r0 = sOut[cell * 49 + 4 * k + 0];
            const float r1 = sOut[cell * 49 + 4 * k + 1];
            const float r2 = sOut[cell * 49 + 4 * k + 2];
            const float r3 = sOut[cell * 49 + 4 * k + 3];
            const float lg = sOut[cell * 49 + 36 + k];
            const float BW = (k % 3 == 0) ? 2.f : ((k % 3 == 1) ? 4.f : 8.f);
            const float BH = (k / 3 == 0) ? 2.f : ((k / 3 == 1) ? 4.f : 8.f);
            const float wc = fx * 16.f + r0;
            const float hc = fy * 16.f + r1;
            const float wa = wc + BW * r2;
            const float ha = hc + BH * r3;
            const float ob = 1.f / (1.f + __expf(-lg));
            float* o = sStage + (cell * 9 + k) * 7;
            o[0] = wc; o[1] = hc; o[2] = wa; o[3] = ha;
            o[4] = bb; o[5] = ob; o[6] = (float)k;
        }
    }
    __syncthreads();

    float* obase = out + (size_t)bidx * 16128;
    #pragma unroll
    for (int i = 0; i < 42; ++i)
        obase[tid + 384 * i] = sStage[tid + 384 * i];
}

// ---------------------------------------------------------------------------
extern "C" void kernel_launch(void* const* d_in, const int* in_sizes, int n_in,
                              void* d_out, int out_size)
{
    const float* img     = (const float*)d_in[0];
    const float* w_patch = (const float*)d_in[1];
    const float* w_reg   = (const float*)d_in[2];
    const float* b_reg   = (const float*)d_in[3];
    const float* w_obj   = (const float*)d_in[4];
    const float* b_obj   = (const float*)d_in[5];
    float* out = (float*)d_out;

    kA1<<<dim3(48, 8), 192>>>(w_patch, w_reg, w_obj);
    kA2<<<36, 256>>>();

    const size_t SMEM = (size_t)(DIMD * NJ + 2 * 16 * CP + 48) * sizeof(float); // 181440
    cudaFuncSetAttribute(kB, cudaFuncAttributeMaxDynamicSharedMemorySize, (int)SMEM);
    kB<<<128, 384, SMEM>>>(img, b_reg, b_obj, out);
}

// round 4
// speedup vs baseline: 1.4623x; 1.4282x over previous
#include <cuda_runtime.h>
#include <cuda_bf16.h>
#include <cstdint>

// ============================================================================
// out = patches @ (w_patch @ [w_reg|w_obj]) + bias, anchor decode.
//   kA1: W2 partials (grid 24x32, block 384)
//   kA2: reduce 32 partials -> g_Bfrag (bf16 in per-lane HMMA fragment order)
//   kB : mma.sync bf16 HMMA GEMM (M=256 cells/CTA, N=48, K=768) + decode
// No tcgen05 (unavailable at compute_103) — portable HMMA path.
// ============================================================================

__device__ float g_part[32 * 768 * 48];                 // 4.7 MB partials
__device__ __align__(16) unsigned int g_Bfrag[48 * 6 * 32 * 2]; // B frags (u32 = bf16x2)

__device__ __forceinline__ uint32_t smem_u32(const void* p) {
    uint32_t a;
    asm("{ .reg .u64 t; cvta.to.shared.u64 t, %1; cvt.u32.u64 %0, t; }"
        : "=r"(a) : "l"(p));
    return a;
}

// ---------------------------------------------------------------------------
// kA1: grid (24, 32), block 384. CTA = 32 pc-rows x 24 d-chunk x 48 j.
// ---------------------------------------------------------------------------
__global__ void __launch_bounds__(384) kA1(const float* __restrict__ w_patch,
                                           const float* __restrict__ w_reg,
                                           const float* __restrict__ w_obj)
{
    __shared__ __align__(16) float sWc[24 * 48];
    __shared__ float sWp[32 * 25];

    const int tid = threadIdx.x;
    const int r0  = blockIdx.x * 32;
    const int d0  = blockIdx.y * 24;

    #pragma unroll
    for (int i = tid; i < 24 * 48; i += 384) {
        int d = i / 48, j = i % 48;
        float v = 0.f;
        if (j < 36)       v = w_reg[(size_t)(d0 + d) * 36 + j];
        else if (j < 45)  v = w_obj[(size_t)(d0 + d) * 9 + (j - 36)];
        sWc[i] = v;
    }
    #pragma unroll
    for (int i = tid; i < 32 * 24; i += 384) {
        int r = i / 24, d = i % 24;
        sWp[r * 25 + d] = w_patch[(size_t)(r0 + r) * 768 + d0 + d];
    }
    __syncthreads();

    const int rl = tid / 12;
    const int jq = tid % 12;
    float4 acc = make_float4(0.f, 0.f, 0.f, 0.f);
    #pragma unroll
    for (int dd = 0; dd < 24; ++dd) {
        float a = sWp[rl * 25 + dd];
        float4 w = *(const float4*)&sWc[dd * 48 + jq * 4];
        acc.x += a * w.x; acc.y += a * w.y; acc.z += a * w.z; acc.w += a * w.w;
    }
    ((float4*)g_part)[((size_t)blockIdx.y * 768 + r0 + rl) * 12 + jq] = acc;
}

// ---------------------------------------------------------------------------
// kA2: reduce 32 partials; write bf16 B in mma.m16n8k16 fragment order:
//   W2[pc][j]: ks=pc>>4, k=pc&15, ntile=j>>3, lane=((j&7)<<2)|((k>>1)&3),
//   reg=k>>3, half=k&1.
// ---------------------------------------------------------------------------
__global__ void kA2()
{
    int t = blockIdx.x * 256 + threadIdx.x;   // 36864 = (pc, j)
    if (t >= 36864) return;
    float s = 0.f;
    #pragma unroll
    for (int p = 0; p < 32; ++p) s += g_part[p * 36864 + t];

    int pc = t / 48, j = t % 48;
    int ks = pc >> 4, k = pc & 15;
    int tf = j >> 3;
    int lane = ((j & 7) << 2) | ((k >> 1) & 3);
    int reg  = k >> 3;
    int half = k & 1;
    __nv_bfloat16 v = __float2bfloat16_rn(s);
    unsigned short* dst = (unsigned short*)g_Bfrag;
    dst[(((ks * 6 + tf) * 32 + lane) * 2 + reg) * 2 + half] = *(unsigned short*)&v;
}

// ---------------------------------------------------------------------------
// kB: grid 128 (b*4 + fyq), block 512. 256 cells/CTA (8 fy x 32 fx).
// Warp w -> cells 16w..16w+15. 48 k-steps (c,py), m16n8k16 HMMA, N=48.
// smem: A double buffer 2x12288B at offset 0 (rows stride 48B, conflict-free
// ldmatrix); epilogue reuses [0,50176) as sOut[256][49]; bias at 50176.
// ---------------------------------------------------------------------------
#define ABUF   12288
#define BIAS_OFF 50176
#define SMEMB  50432

__global__ void __launch_bounds__(512, 1) kB(
    const float* __restrict__ img,
    const float* __restrict__ b_reg,
    const float* __restrict__ b_obj,
    float* __restrict__ out)
{
    extern __shared__ __align__(16) char sm[];
    const uint32_t smem = smem_u32(sm);
    const int tid = threadIdx.x;
    const int b   = blockIdx.x >> 2;
    const int fyq = blockIdx.x & 3;

    float* sBias = (float*)(sm + BIAS_OFF);
    if (tid < 48)
        sBias[tid] = (tid < 36) ? b_reg[tid] : ((tid < 45) ? b_obj[tid - 36] : 0.f);

    // loader mapping: thread -> (img row fyl = tid>>6, 8 floats at x = seg*8)
    const int fyl = tid >> 6;
    const int seg = tid & 63;
    const int cell_w = fyl * 32 + (seg >> 1);
    const uint32_t soff = (uint32_t)cell_w * 48 + (seg & 1) * 16;

    // mma mapping
    const int wid  = tid >> 5;
    const int lane = tid & 31;
    const uint32_t lm_off = (lane < 16)
        ? (uint32_t)(16 * wid + lane) * 48
        : (uint32_t)(16 * wid + lane - 16) * 48 + 16;

    float d[6][4];
    #pragma unroll
    for (int t = 0; t < 6; ++t)
        #pragma unroll
        for (int q = 0; q < 4; ++q) d[t][q] = 0.f;

    // img float4 base for a step s: c = s>>4, py = s&15
    #define SRC(s) ((const float4*)(img + \
        (((size_t)b * 3 + ((s) >> 4)) * 512 + (size_t)((fyq * 8 + fyl) * 16 + ((s) & 15))) * 512) + seg * 2)

    float4 va0, va1, vb0, vb1;
    { const float4* p = SRC(0); va0 = p[0]; va1 = p[1]; }
    { const float4* p = SRC(1); vb0 = p[0]; vb1 = p[1]; }

    #define STS(u, v, buf) do {                                               \
        __nv_bfloat162 p0 = __float22bfloat162_rn(make_float2((u).x, (u).y)); \
        __nv_bfloat162 p1 = __float22bfloat162_rn(make_float2((u).z, (u).w)); \
        __nv_bfloat162 p2 = __float22bfloat162_rn(make_float2((v).x, (v).y)); \
        __nv_bfloat162 p3 = __float22bfloat162_rn(make_float2((v).z, (v).w)); \
        asm volatile("st.shared.v4.b32 [%0], {%1,%2,%3,%4};" ::               \
            "r"(smem + (buf) * ABUF + soff),                                  \
            "r"(*(uint32_t*)&p0), "r"(*(uint32_t*)&p1),                       \
            "r"(*(uint32_t*)&p2), "r"(*(uint32_t*)&p3) : "memory");           \
    } while (0)

    STS(va0, va1, 0);
    __syncthreads();

    const uint2* __restrict__ Bf = (const uint2*)g_Bfrag;

    for (int s = 0; s < 48; ++s) {
        // prefetch step s+2
        if (s + 2 < 48) {
            const float4* p = SRC(s + 2);
            if ((s & 1) == 0) { va0 = p[0]; va1 = p[1]; }
            else              { vb0 = p[0]; vb1 = p[1]; }
        }

        // compute step s from buf s&1
        uint32_t a0, a1, a2, a3;
        asm volatile("ldmatrix.sync.aligned.m8n8.x4.shared.b16 {%0,%1,%2,%3}, [%4];"
            : "=r"(a0), "=r"(a1), "=r"(a2), "=r"(a3)
            : "r"(smem + (s & 1) * ABUF + lm_off));
        #pragma unroll
        for (int t = 0; t < 6; ++t) {
            uint2 bb = __ldg(&Bf[(s * 6 + t) * 32 + lane]);
            asm volatile(
                "mma.sync.aligned.m16n8k16.row.col.f32.bf16.bf16.f32 "
                "{%0,%1,%2,%3}, {%4,%5,%6,%7}, {%8,%9}, {%0,%1,%2,%3};"
                : "+f"(d[t][0]), "+f"(d[t][1]), "+f"(d[t][2]), "+f"(d[t][3])
                : "r"(a0), "r"(a1), "r"(a2), "r"(a3), "r"(bb.x), "r"(bb.y));
        }

        // store step s+1 into buf (s+1)&1
        if (s + 1 < 48) {
            if ((s & 1) == 0) STS(vb0, vb1, 1);
            else              STS(va0, va1, 0);
        }
        __syncthreads();
    }

    // ---- epilogue: scatter accums to sOut[256][49] (+bias) ----
    float* sOut = (float*)sm;
    {
        const int g  = lane >> 2;
        const int tg = lane & 3;
        #pragma unroll
        for (int cc = 0; cc < 2; ++cc) {
            const int cell = wid * 16 + g + cc * 8;
            #pragma unroll
            for (int t = 0; t < 6; ++t) {
                const int j = t * 8 + tg * 2;
                sOut[cell * 49 + j]     = d[t][2 * cc]     + sBias[j];
                sOut[cell * 49 + j + 1] = d[t][2 * cc + 1] + sBias[j + 1];
            }
        }
    }
    __syncthreads();

    // ---- decode + coalesced store: 16128 floats ----
    float* obase = out + (size_t)blockIdx.x * 16128;
    const float bb_f = (float)b;
    #pragma unroll
    for (int i = 0; i < 32; ++i) {
        int idx = tid + 512 * i;
        if (idx < 16128) {
            int cell = idx / 63;
            int r    = idx - cell * 63;
            int k    = r / 7;
            int q    = r - k * 7;
            const float* v = sOut + cell * 49;
            float res;
            if (q == 0)      res = (float)(cell & 31) * 16.f + v[4 * k];
            else if (q == 1) res = (float)(fyq * 8 + (cell >> 5)) * 16.f + v[4 * k + 1];
            else if (q == 2) res = (float)(cell & 31) * 16.f + v[4 * k]
                                   + (float)(2 << (k % 3)) * v[4 * k + 2];
            else if (q == 3) res = (float)(fyq * 8 + (cell >> 5)) * 16.f + v[4 * k + 1]
                                   + (float)(2 << (k / 3)) * v[4 * k + 3];
            else if (q == 4) res = bb_f;
            else if (q == 5) res = 1.f / (1.f + __expf(-v[36 + k]));
            else             res = (float)k;
            obase[idx] = res;
        }
    }
}

// ---------------------------------------------------------------------------
extern "C" void kernel_launch(void* const* d_in, const int* in_sizes, int n_in,
                              void* d_out, int out_size)
{
    const float* img     = (const float*)d_in[0];
    const float* w_patch = (const float*)d_in[1];
    const float* w_reg   = (const float*)d_in[2];
    const float* b_reg   = (const float*)d_in[3];
    const float* w_obj   = (const float*)d_in[4];
    const float* b_obj   = (const float*)d_in[5];
    float* out = (float*)d_out;

    kA1<<<dim3(24, 32), 384>>>(w_patch, w_reg, w_obj);
    kA2<<<144, 256>>>();

    cudaFuncSetAttribute(kB, cudaFuncAttributeMaxDynamicSharedMemorySize, SMEMB);
    kB<<<128, 512, SMEMB>>>(img, b_reg, b_obj, out);
}